// round 15
// baseline (speedup 1.0000x reference)
#include <cuda_runtime.h>
#include <cuda_fp16.h>
#include <cstdint>

#define BATCH 32768
#define HDIM  512
#define MD    8
#define CDIM  1024
#define NCAT  262144
#define KDIM  532
#define KP    544            // 8*64 + 32
#define NKIT  9              // 8 full chunks of 64 + 1 half chunk of 32
#define EPS   1e-6f

// ---------------- static scratch ----------------
__device__ float g_sums[BATCH * MD];
__device__ float g_counts[BATCH];
__device__ float g_meta[BATCH * 20];
__device__ float g_bias6[BATCH * 6];
__device__ __half g_x[(size_t)BATCH * KP];     // 35.7 MB
__device__ __half g_w[CDIM * KP];              // 1.1 MB
__device__ __half g_feat[(size_t)BATCH * CDIM];// 64 MB

// ---------------- helpers ----------------
__device__ __forceinline__ float warp_sum(float v) {
#pragma unroll
    for (int o = 16; o > 0; o >>= 1) v += __shfl_xor_sync(0xffffffffu, v, o);
    return v;
}
__device__ __forceinline__ uint32_t smem_u32(const void* p) {
    uint32_t a;
    asm("{ .reg .u64 t; cvta.to.shared.u64 t, %1; cvt.u32.u64 %0, t; }" : "=r"(a) : "l"(p));
    return a;
}
__device__ __forceinline__ void cp16(uint32_t dst, const void* src) {
    unsigned long long g = (unsigned long long)__cvta_generic_to_global(src);
    asm volatile("cp.async.cg.shared.global [%0], [%1], 16;" :: "r"(dst), "l"(g) : "memory");
}
__device__ __forceinline__ void cp_commit() {
    asm volatile("cp.async.commit_group;" ::: "memory");
}
template <int N>
__device__ __forceinline__ void cp_wait() {
    asm volatile("cp.async.wait_group %0;" :: "n"(N) : "memory");
}
__device__ __forceinline__ void ldsm4(uint32_t* r, uint32_t addr) {
    asm volatile("ldmatrix.sync.aligned.m8n8.x4.shared.b16 {%0,%1,%2,%3}, [%4];"
                 : "=r"(r[0]), "=r"(r[1]), "=r"(r[2]), "=r"(r[3]) : "r"(addr));
}
__device__ __forceinline__ void mma16816(float* d, const uint32_t* a, const uint32_t* b) {
    asm volatile(
        "mma.sync.aligned.m16n8k16.row.col.f32.f16.f16.f32 "
        "{%0,%1,%2,%3}, {%4,%5,%6,%7}, {%8,%9}, {%0,%1,%2,%3};"
        : "+f"(d[0]), "+f"(d[1]), "+f"(d[2]), "+f"(d[3])
        : "r"(a[0]), "r"(a[1]), "r"(a[2]), "r"(a[3]), "r"(b[0]), "r"(b[1]));
}

// ---------------- K0: zero segment scratch ----------------
__global__ void zero_kernel() {
    int i = blockIdx.x * blockDim.x + threadIdx.x;
    if (i < BATCH * MD) g_sums[i] = 0.0f;
    if (i < BATCH) g_counts[i] = 0.0f;
}

// ---------------- K1: ragged segment sum (run-length, sorted cat_seg) ----------------
__global__ void seg_kernel(const float* __restrict__ meta_table,
                           const int* __restrict__ cat_ids,
                           const int* __restrict__ cat_seg) {
    int t = blockIdx.x * blockDim.x + threadIdx.x;
    int base = t * 8;
    if (base >= NCAT) return;

    float acc[MD];
#pragma unroll
    for (int d = 0; d < MD; d++) acc[d] = 0.0f;
    float cnt = 0.0f;
    int cur = cat_seg[base];

    for (int i = 0; i < 8; i++) {
        int s = cat_seg[base + i];
        int c = cat_ids[base + i];
        const float* e = meta_table + (size_t)c * MD;
        if (s != cur) {
#pragma unroll
            for (int d = 0; d < MD; d++) atomicAdd(&g_sums[cur * MD + d], acc[d]);
            atomicAdd(&g_counts[cur], cnt);
#pragma unroll
            for (int d = 0; d < MD; d++) acc[d] = 0.0f;
            cnt = 0.0f;
            cur = s;
        }
#pragma unroll
        for (int d = 0; d < MD; d++) acc[d] += e[d];
        cnt += 1.0f;
    }
#pragma unroll
    for (int d = 0; d < MD; d++) atomicAdd(&g_sums[cur * MD + d], acc[d]);
    atomicAdd(&g_counts[cur], cnt);
}

// ---------------- K2: conv/relu/maxpool + credit biases ----------------
__global__ void meta_kernel(const float* __restrict__ meta_table,
                            const float* __restrict__ conv_w,
                            const float* __restrict__ conv_b,
                            const int* __restrict__ meta_ids,
                            const float* __restrict__ credit) {
    int b = blockIdx.x * blockDim.x + threadIdx.x;
    if (b >= BATCH) return;

    float mat[6][MD];
    float cnt = fmaxf(g_counts[b], 1.0f);
#pragma unroll
    for (int d = 0; d < MD; d++) mat[0][d] = g_sums[b * MD + d] / cnt;
#pragma unroll
    for (int r = 0; r < 5; r++) {
        int id = meta_ids[b * 5 + r];
        const float* e = meta_table + (size_t)id * MD;
#pragma unroll
        for (int d = 0; d < MD; d++) mat[r + 1][d] = e[d];
    }
    float conv[5][6];
#pragma unroll
    for (int o = 0; o < 5; o++) {
#pragma unroll
        for (int t = 0; t < 6; t++) {
            float a = conv_b[o];
#pragma unroll
            for (int i = 0; i < 6; i++)
#pragma unroll
                for (int k = 0; k < 3; k++)
                    a += mat[i][t + k] * conv_w[o * 18 + i * 3 + k];
            conv[o][t] = fmaxf(a, 0.0f);
        }
    }
#pragma unroll
    for (int o = 0; o < 5; o++)
#pragma unroll
        for (int t = 0; t < 4; t++)
            g_meta[b * 20 + o * 4 + t] =
                fmaxf(fmaxf(conv[o][t], conv[o][t + 1]), conv[o][t + 2]);

    float cv[6], s = 0.0f;
#pragma unroll
    for (int c = 0; c < 6; c++) { cv[c] = credit[b * 6 + c]; s += cv[c]; }
#pragma unroll
    for (int c = 0; c < 6; c++)
        g_bias6[b * 6 + c] = (s > 0.0f) ? cv[c] / s : (1.0f / 6.0f);
}

// ---------------- K3: LN1 -> fp16, vectorized, K padded to 544 ----------------
__global__ __launch_bounds__(256) void ln1_kernel(const float* __restrict__ encode,
                                                  const float* __restrict__ g1,
                                                  const float* __restrict__ b1) {
    int warp = threadIdx.x >> 5;
    int lane = threadIdx.x & 31;
    int row = blockIdx.x * 8 + warp;

    const float4* e4 = (const float4*)(encode + (size_t)row * HDIM);
    float4 v[4];
#pragma unroll
    for (int g = 0; g < 4; g++) v[g] = e4[g * 32 + lane];
    float m = (lane < 20) ? g_meta[row * 20 + lane] : 0.0f;

    float s = m;
#pragma unroll
    for (int g = 0; g < 4; g++) s += v[g].x + v[g].y + v[g].z + v[g].w;
    s = warp_sum(s);
    float mu = s * (1.0f / KDIM);

    float sq = (lane < 20) ? (m - mu) * (m - mu) : 0.0f;
#pragma unroll
    for (int g = 0; g < 4; g++) {
        float dx = v[g].x - mu, dy = v[g].y - mu, dz = v[g].z - mu, dw = v[g].w - mu;
        sq += dx * dx + dy * dy + dz * dz + dw * dw;
    }
    sq = warp_sum(sq);
    float rs = rsqrtf(sq * (1.0f / KDIM) + EPS);

    __half* dx = g_x + (size_t)row * KP;
#pragma unroll
    for (int g = 0; g < 4; g++) {
        int j = g * 128 + lane * 4;
        float4 gg = *(const float4*)(g1 + j);
        float4 bb = *(const float4*)(b1 + j);
        float y0 = gg.x * (v[g].x - mu) * rs + bb.x;
        float y1 = gg.y * (v[g].y - mu) * rs + bb.y;
        float y2 = gg.z * (v[g].z - mu) * rs + bb.z;
        float y3 = gg.w * (v[g].w - mu) * rs + bb.w;
        __half2 h01 = __floats2half2_rn(y0, y1);
        __half2 h23 = __floats2half2_rn(y2, y3);
        uint2 pk;
        pk.x = *(uint32_t*)&h01;
        pk.y = *(uint32_t*)&h23;
        *(uint2*)(dx + j) = pk;
    }
    // meta tail (512..531) + zero pad (532..543)
    float ym = 0.0f;
    if (lane < 20) ym = g1[512 + lane] * (m - mu) * rs + b1[512 + lane];
    dx[512 + lane] = __float2half(ym);
}

// ---------------- K4: W1 -> fp16, padded ----------------
__global__ void wconv_kernel(const float* __restrict__ w) {
    int idx = blockIdx.x * blockDim.x + threadIdx.x;
    if (idx >= CDIM * KP) return;
    int n = idx / KP;
    int k = idx - n * KP;
    float v = (k < KDIM) ? w[(size_t)n * KDIM + k] : 0.0f;
    g_w[idx] = __float2half(v);
}

// ---------------- K5: fp16 GEMM  feat = relu(x @ W^T + b) ----------------
// CTA 256x128, 256 threads (8 warps), warp tile 64x64, K-chunk 64 (last chunk 32),
// 3-stage cp.async, register double-buffering of ldmatrix fragments.
#define A_ROWS  256
#define B_ROWS  128
#define ROW_B   144
#define A_STG   (A_ROWS * ROW_B)           // 36864
#define B_STG   (B_ROWS * ROW_B)           // 18432
#define STG     (A_STG + B_STG)            // 55296
#define NSTAGE  3
#define SMEM_TOT (NSTAGE * STG)            // 165888

__global__ __launch_bounds__(256, 1) void gemm1_mma(const float* __restrict__ bias) {
    extern __shared__ char sm[];
    int tid = threadIdx.x;
    int lane = tid & 31;
    int w = tid >> 5;
    int wm = (w & 3) * 64;      // 4 M-warps
    int wn = (w >> 2) * 64;     // 2 N-warps

    int m0 = blockIdx.y * A_ROWS;
    int n0 = blockIdx.x * B_ROWS;

    uint32_t sbase = smem_u32(sm);

    float acc[4][8][4];
#pragma unroll
    for (int i = 0; i < 4; i++)
#pragma unroll
        for (int j = 0; j < 8; j++)
#pragma unroll
            for (int q = 0; q < 4; q++) acc[i][j][q] = 0.0f;

    auto load_stage = [&](int st, int kc) {
        uint32_t sa = sbase + st * STG;
        uint32_t sb = sa + A_STG;
        int ko = kc * 64;
        bool full = (kc < 8);   // last chunk has only 32 valid K (4 x 16B chunks)
#pragma unroll
        for (int i = 0; i < 8; i++) {
            int idx = i * 256 + tid;
            int row = idx >> 3, c = idx & 7;
            if (full || c < 4)
                cp16(sa + row * ROW_B + c * 16,
                     g_x + (size_t)(m0 + row) * KP + ko + c * 8);
        }
#pragma unroll
        for (int i = 0; i < 4; i++) {
            int idx = i * 256 + tid;
            int row = idx >> 3, c = idx & 7;
            if (full || c < 4)
                cp16(sb + row * ROW_B + c * 16,
                     g_w + (size_t)(n0 + row) * KP + ko + c * 8);
        }
        cp_commit();
    };

    load_stage(0, 0);
    load_stage(1, 1);

    int lrow = lane & 15;
    int acol = (lane >> 4) * 16;
    int b_lrow = (lane & 7) + ((lane >> 4) & 1) * 8;
    int b_lcol = ((lane >> 3) & 1) * 16;

    for (int kc = 0; kc < NKIT; kc++) {
        if (kc + 2 < NKIT) { load_stage((kc + 2) % NSTAGE, kc + 2); cp_wait<2>(); }
        else if (kc + 1 < NKIT) cp_wait<1>();
        else cp_wait<0>();
        __syncthreads();

        uint32_t sa = sbase + (kc % NSTAGE) * STG;
        uint32_t sb = sa + A_STG;
        int kkmax = (kc == 8) ? 2 : 4;

        uint32_t aCur[4][4], aNxt[4][4], bCur[4], bNxt[4];
        // prologue frags: kk=0
#pragma unroll
        for (int t = 0; t < 4; t++)
            ldsm4(aCur[t], sa + (wm + t * 16 + lrow) * ROW_B + acol);
        ldsm4(bCur, sb + (wn + b_lrow) * ROW_B + b_lcol);

#pragma unroll
        for (int kk = 0; kk < 4; kk++) {
            if (kk == kkmax) break;
            int kb = kk * 32;
            if (kk < 3) {
#pragma unroll
                for (int t = 0; t < 4; t++)
                    ldsm4(aNxt[t], sa + (wm + t * 16 + lrow) * ROW_B + kb + 32 + acol);
            }
#pragma unroll
            for (int jj = 0; jj < 4; jj++) {
                if (jj < 3)
                    ldsm4(bNxt, sb + (wn + (jj + 1) * 16 + b_lrow) * ROW_B + kb + b_lcol);
                else if (kk < 3)
                    ldsm4(bNxt, sb + (wn + b_lrow) * ROW_B + kb + 32 + b_lcol);

                uint32_t be[2] = {bCur[0], bCur[1]}, bo[2] = {bCur[2], bCur[3]};
                int je = jj * 2, jo = jj * 2 + 1;
#pragma unroll
                for (int t = 0; t < 4; t++) {
                    mma16816(acc[t][je], aCur[t], be);
                    mma16816(acc[t][jo], aCur[t], bo);
                }
#pragma unroll
                for (int z = 0; z < 4; z++) bCur[z] = bNxt[z];
            }
            if (kk < 3) {
#pragma unroll
                for (int t = 0; t < 4; t++)
#pragma unroll
                    for (int z = 0; z < 4; z++) aCur[t][z] = aNxt[t][z];
            }
        }
        __syncthreads();
    }

    // ---- epilogue: bias + relu -> g_feat (fp16) ----
    int r2 = lane >> 2, c2 = (lane & 3) * 2;
#pragma unroll
    for (int t = 0; t < 4; t++) {
        int row0 = m0 + wm + t * 16 + r2;
#pragma unroll
        for (int j = 0; j < 8; j++) {
            int col = n0 + wn + j * 8 + c2;
            float b0 = bias[col], b1 = bias[col + 1];
            __half2 v0 = __floats2half2_rn(fmaxf(acc[t][j][0] + b0, 0.0f),
                                           fmaxf(acc[t][j][1] + b1, 0.0f));
            __half2 v1 = __floats2half2_rn(fmaxf(acc[t][j][2] + b0, 0.0f),
                                           fmaxf(acc[t][j][3] + b1, 0.0f));
            *(__half2*)(g_feat + (size_t)row0 * CDIM + col) = v0;
            *(__half2*)(g_feat + (size_t)(row0 + 8) * CDIM + col) = v1;
        }
    }
}

// ---------------- K6: LN2 + output GEMM (6 cols) + biases ----------------
// 1024 threads/block (32 rows) to amortize the out_w shared-load across 4x rows.
__global__ __launch_bounds__(1024) void out_kernel(const float* __restrict__ g2,
                                                   const float* __restrict__ b2,
                                                   const float* __restrict__ out_w,
                                                   const float* __restrict__ out_b,
                                                   float* __restrict__ out) {
    __shared__ float sw[6 * CDIM];
    for (int i = threadIdx.x; i < 6 * CDIM; i += 1024) sw[i] = out_w[i];
    __syncthreads();

    int warp = threadIdx.x >> 5;
    int lane = threadIdx.x & 31;
    int row = blockIdx.x * 32 + warp;

    const uint2* f4 = (const uint2*)(g_feat + (size_t)row * CDIM);
    float2 v[16];
    float s = 0.0f;
#pragma unroll
    for (int k = 0; k < 8; k++) {
        uint2 raw = f4[lane + k * 32];
        __half2 lo = *(__half2*)&raw.x;
        __half2 hi = *(__half2*)&raw.y;
        v[2 * k]     = __half22float2(lo);
        v[2 * k + 1] = __half22float2(hi);
        s += v[2 * k].x + v[2 * k].y + v[2 * k + 1].x + v[2 * k + 1].y;
    }
    s = warp_sum(s);
    float mu = s * (1.0f / CDIM);
    float sq = 0.0f;
#pragma unroll
    for (int k = 0; k < 16; k++) {
        float dx = v[k].x - mu, dy = v[k].y - mu;
        sq += dx * dx + dy * dy;
    }
    sq = warp_sum(sq);
    float rs = rsqrtf(sq * (1.0f / CDIM) + EPS);

    float acc[6] = {0, 0, 0, 0, 0, 0};
#pragma unroll
    for (int k = 0; k < 8; k++) {
        int j = (lane + k * 32) * 4;
        float4 gg = *(const float4*)(g2 + j);
        float4 bb = *(const float4*)(b2 + j);
        float y0 = gg.x * (v[2 * k].x - mu) * rs + bb.x;
        float y1 = gg.y * (v[2 * k].y - mu) * rs + bb.y;
        float y2 = gg.z * (v[2 * k + 1].x - mu) * rs + bb.z;
        float y3 = gg.w * (v[2 * k + 1].y - mu) * rs + bb.w;
#pragma unroll
        for (int c = 0; c < 6; c++) {
            const float* swc = sw + c * CDIM + j;
            acc[c] += y0 * swc[0] + y1 * swc[1] + y2 * swc[2] + y3 * swc[3];
        }
    }
#pragma unroll
    for (int c = 0; c < 6; c++) acc[c] = warp_sum(acc[c]);

    if (lane == 0) {
#pragma unroll
        for (int c = 0; c < 6; c++)
            out[row * 6 + c] = acc[c] + out_b[c] + g_bias6[row * 6 + c];
    }
}

// ---------------- launch ----------------
extern "C" void kernel_launch(void* const* d_in, const int* in_sizes, int n_in,
                              void* d_out, int out_size) {
    const float* encode     = (const float*)d_in[0];
    const float* credit_vec = (const float*)d_in[1];
    const float* meta_table = (const float*)d_in[2];
    const float* conv_w     = (const float*)d_in[3];
    const float* conv_b     = (const float*)d_in[4];
    const float* ln1_g      = (const float*)d_in[5];
    const float* ln1_b      = (const float*)d_in[6];
    const float* mlp1_w     = (const float*)d_in[7];
    const float* mlp1_b     = (const float*)d_in[8];
    const float* ln2_g      = (const float*)d_in[9];
    const float* ln2_b      = (const float*)d_in[10];
    const float* out_w      = (const float*)d_in[11];
    const float* out_b      = (const float*)d_in[12];
    const int*   meta_ids   = (const int*)d_in[13];
    const int*   cat_ids    = (const int*)d_in[14];
    const int*   cat_seg    = (const int*)d_in[15];
    float* out = (float*)d_out;

    static bool init = false;
    if (!init) {
        cudaFuncSetAttribute(gemm1_mma, cudaFuncAttributeMaxDynamicSharedMemorySize, SMEM_TOT);
        init = true;
    }

    zero_kernel<<<(BATCH * MD + 255) / 256, 256>>>();
    seg_kernel<<<(NCAT / 8 + 255) / 256, 256>>>(meta_table, cat_ids, cat_seg);
    meta_kernel<<<(BATCH + 127) / 128, 128>>>(meta_table, conv_w, conv_b, meta_ids, credit_vec);
    ln1_kernel<<<BATCH / 8, 256>>>(encode, ln1_g, ln1_b);
    wconv_kernel<<<(CDIM * KP + 255) / 256, 256>>>(mlp1_w);
    {
        dim3 grid(CDIM / B_ROWS, BATCH / A_ROWS);   // (8, 128), N fastest
        gemm1_mma<<<grid, 256, SMEM_TOT>>>(mlp1_b);
    }
    out_kernel<<<BATCH / 32, 1024>>>(ln2_g, ln2_b, out_w, out_b, out);
}

// round 16
// speedup vs baseline: 1.0554x; 1.0554x over previous
#include <cuda_runtime.h>
#include <cuda_fp16.h>
#include <cstdint>

#define BATCH 32768
#define HDIM  512
#define MD    8
#define CDIM  1024
#define NCAT  262144
#define KDIM  532
#define KP    576            // K padded to 9*64
#define NKIT  9              // chunks of K=64
#define EPS   1e-6f

// ---------------- static scratch ----------------
__device__ float g_sums[BATCH * MD];
__device__ float g_counts[BATCH];
__device__ float g_meta[BATCH * 20];
__device__ float g_bias6[BATCH * 6];
__device__ __half g_x[(size_t)BATCH * KP];     // 37.7 MB
__device__ __half g_w[CDIM * KP];              // 1.2 MB
__device__ __half g_feat[(size_t)BATCH * CDIM];// 64 MB

// ---------------- helpers ----------------
__device__ __forceinline__ float warp_sum(float v) {
#pragma unroll
    for (int o = 16; o > 0; o >>= 1) v += __shfl_xor_sync(0xffffffffu, v, o);
    return v;
}
__device__ __forceinline__ uint32_t smem_u32(const void* p) {
    uint32_t a;
    asm("{ .reg .u64 t; cvta.to.shared.u64 t, %1; cvt.u32.u64 %0, t; }" : "=r"(a) : "l"(p));
    return a;
}
__device__ __forceinline__ void cp16(uint32_t dst, const void* src) {
    unsigned long long g = (unsigned long long)__cvta_generic_to_global(src);
    asm volatile("cp.async.cg.shared.global [%0], [%1], 16;" :: "r"(dst), "l"(g) : "memory");
}
__device__ __forceinline__ void cp_commit() {
    asm volatile("cp.async.commit_group;" ::: "memory");
}
template <int N>
__device__ __forceinline__ void cp_wait() {
    asm volatile("cp.async.wait_group %0;" :: "n"(N) : "memory");
}
__device__ __forceinline__ void ldsm4(uint32_t* r, uint32_t addr) {
    asm volatile("ldmatrix.sync.aligned.m8n8.x4.shared.b16 {%0,%1,%2,%3}, [%4];"
                 : "=r"(r[0]), "=r"(r[1]), "=r"(r[2]), "=r"(r[3]) : "r"(addr));
}
__device__ __forceinline__ void mma16816(float* d, const uint32_t* a, const uint32_t* b) {
    asm volatile(
        "mma.sync.aligned.m16n8k16.row.col.f32.f16.f16.f32 "
        "{%0,%1,%2,%3}, {%4,%5,%6,%7}, {%8,%9}, {%0,%1,%2,%3};"
        : "+f"(d[0]), "+f"(d[1]), "+f"(d[2]), "+f"(d[3])
        : "r"(a[0]), "r"(a[1]), "r"(a[2]), "r"(a[3]), "r"(b[0]), "r"(b[1]));
}

// ---------------- K0: zero segment scratch ----------------
__global__ void zero_kernel() {
    int i = blockIdx.x * blockDim.x + threadIdx.x;
    if (i < BATCH * MD) g_sums[i] = 0.0f;
    if (i < BATCH) g_counts[i] = 0.0f;
}

// ---------------- K1: ragged segment sum (run-length, sorted cat_seg) ----------------
__global__ void seg_kernel(const float* __restrict__ meta_table,
                           const int* __restrict__ cat_ids,
                           const int* __restrict__ cat_seg) {
    int t = blockIdx.x * blockDim.x + threadIdx.x;
    int base = t * 8;
    if (base >= NCAT) return;

    float acc[MD];
#pragma unroll
    for (int d = 0; d < MD; d++) acc[d] = 0.0f;
    float cnt = 0.0f;
    int cur = cat_seg[base];

    for (int i = 0; i < 8; i++) {
        int s = cat_seg[base + i];
        int c = cat_ids[base + i];
        const float* e = meta_table + (size_t)c * MD;
        if (s != cur) {
#pragma unroll
            for (int d = 0; d < MD; d++) atomicAdd(&g_sums[cur * MD + d], acc[d]);
            atomicAdd(&g_counts[cur], cnt);
#pragma unroll
            for (int d = 0; d < MD; d++) acc[d] = 0.0f;
            cnt = 0.0f;
            cur = s;
        }
#pragma unroll
        for (int d = 0; d < MD; d++) acc[d] += e[d];
        cnt += 1.0f;
    }
#pragma unroll
    for (int d = 0; d < MD; d++) atomicAdd(&g_sums[cur * MD + d], acc[d]);
    atomicAdd(&g_counts[cur], cnt);
}

// ---------------- K2: conv/relu/maxpool + credit biases ----------------
__global__ void meta_kernel(const float* __restrict__ meta_table,
                            const float* __restrict__ conv_w,
                            const float* __restrict__ conv_b,
                            const int* __restrict__ meta_ids,
                            const float* __restrict__ credit) {
    int b = blockIdx.x * blockDim.x + threadIdx.x;
    if (b >= BATCH) return;

    float mat[6][MD];
    float cnt = fmaxf(g_counts[b], 1.0f);
#pragma unroll
    for (int d = 0; d < MD; d++) mat[0][d] = g_sums[b * MD + d] / cnt;
#pragma unroll
    for (int r = 0; r < 5; r++) {
        int id = meta_ids[b * 5 + r];
        const float* e = meta_table + (size_t)id * MD;
#pragma unroll
        for (int d = 0; d < MD; d++) mat[r + 1][d] = e[d];
    }
    float conv[5][6];
#pragma unroll
    for (int o = 0; o < 5; o++) {
#pragma unroll
        for (int t = 0; t < 6; t++) {
            float a = conv_b[o];
#pragma unroll
            for (int i = 0; i < 6; i++)
#pragma unroll
                for (int k = 0; k < 3; k++)
                    a += mat[i][t + k] * conv_w[o * 18 + i * 3 + k];
            conv[o][t] = fmaxf(a, 0.0f);
        }
    }
#pragma unroll
    for (int o = 0; o < 5; o++)
#pragma unroll
        for (int t = 0; t < 4; t++)
            g_meta[b * 20 + o * 4 + t] =
                fmaxf(fmaxf(conv[o][t], conv[o][t + 1]), conv[o][t + 2]);

    float cv[6], s = 0.0f;
#pragma unroll
    for (int c = 0; c < 6; c++) { cv[c] = credit[b * 6 + c]; s += cv[c]; }
#pragma unroll
    for (int c = 0; c < 6; c++)
        g_bias6[b * 6 + c] = (s > 0.0f) ? cv[c] / s : (1.0f / 6.0f);
}

// ---------------- K3: LN1 -> fp16, vectorized, K padded to 576 ----------------
__global__ __launch_bounds__(256) void ln1_kernel(const float* __restrict__ encode,
                                                  const float* __restrict__ g1,
                                                  const float* __restrict__ b1) {
    int warp = threadIdx.x >> 5;
    int lane = threadIdx.x & 31;
    int row = blockIdx.x * 8 + warp;

    const float4* e4 = (const float4*)(encode + (size_t)row * HDIM);
    float4 v[4];
#pragma unroll
    for (int g = 0; g < 4; g++) v[g] = e4[g * 32 + lane];
    float m = (lane < 20) ? g_meta[row * 20 + lane] : 0.0f;

    float s = m;
#pragma unroll
    for (int g = 0; g < 4; g++) s += v[g].x + v[g].y + v[g].z + v[g].w;
    s = warp_sum(s);
    float mu = s * (1.0f / KDIM);

    float sq = (lane < 20) ? (m - mu) * (m - mu) : 0.0f;
#pragma unroll
    for (int g = 0; g < 4; g++) {
        float dx = v[g].x - mu, dy = v[g].y - mu, dz = v[g].z - mu, dw = v[g].w - mu;
        sq += dx * dx + dy * dy + dz * dz + dw * dw;
    }
    sq = warp_sum(sq);
    float rs = rsqrtf(sq * (1.0f / KDIM) + EPS);

    __half* dx = g_x + (size_t)row * KP;
#pragma unroll
    for (int g = 0; g < 4; g++) {
        int j = g * 128 + lane * 4;
        float4 gg = *(const float4*)(g1 + j);
        float4 bb = *(const float4*)(b1 + j);
        float y0 = gg.x * (v[g].x - mu) * rs + bb.x;
        float y1 = gg.y * (v[g].y - mu) * rs + bb.y;
        float y2 = gg.z * (v[g].z - mu) * rs + bb.z;
        float y3 = gg.w * (v[g].w - mu) * rs + bb.w;
        __half2 h01 = __floats2half2_rn(y0, y1);
        __half2 h23 = __floats2half2_rn(y2, y3);
        uint2 pk;
        pk.x = *(uint32_t*)&h01;
        pk.y = *(uint32_t*)&h23;
        *(uint2*)(dx + j) = pk;
    }
    // meta tail (512..531), zero pad (532..575)
    float ym = 0.0f;
    if (lane < 20) ym = g1[512 + lane] * (m - mu) * rs + b1[512 + lane];
    dx[512 + lane] = __float2half(ym);
    dx[544 + lane] = __float2half(0.0f);
}

// ---------------- K4: W1 -> fp16, padded ----------------
__global__ void wconv_kernel(const float* __restrict__ w) {
    int idx = blockIdx.x * blockDim.x + threadIdx.x;
    if (idx >= CDIM * KP) return;
    int n = idx / KP;
    int k = idx - n * KP;
    float v = (k < KDIM) ? w[(size_t)n * KDIM + k] : 0.0f;
    g_w[idx] = __float2half(v);
}

// ---------------- K5: fp16 GEMM  feat = relu(x @ W^T + b) ----------------
// CTA 128x128, 256 threads (8 warps), warp tile 32x64 (4 M x 2 N warps),
// K-chunk 64, 3-stage cp.async, 2 CTAs/SM (4 warps/SMSP), reg double-buffering.
#define A_ROWS  128
#define B_ROWS  128
#define ROW_B   144
#define A_STG   (A_ROWS * ROW_B)           // 18432
#define B_STG   (B_ROWS * ROW_B)           // 18432
#define STG     (A_STG + B_STG)            // 36864
#define NSTAGE  3
#define SMEM_TOT (NSTAGE * STG)            // 110592 -> 2 CTAs/SM

__global__ __launch_bounds__(256, 2) void gemm1_mma(const float* __restrict__ bias) {
    extern __shared__ char sm[];
    int tid = threadIdx.x;
    int lane = tid & 31;
    int w = tid >> 5;
    int wm = (w & 3) * 32;      // 4 M-warps (32 rows each)
    int wn = (w >> 2) * 64;     // 2 N-warps (64 cols each)

    int m0 = blockIdx.y * A_ROWS;
    int n0 = blockIdx.x * B_ROWS;

    uint32_t sbase = smem_u32(sm);

    float acc[2][8][4];
#pragma unroll
    for (int i = 0; i < 2; i++)
#pragma unroll
        for (int j = 0; j < 8; j++)
#pragma unroll
            for (int q = 0; q < 4; q++) acc[i][j][q] = 0.0f;

    auto load_stage = [&](int st, int kc) {
        uint32_t sa = sbase + st * STG;
        uint32_t sb = sa + A_STG;
        int ko = kc * 64;
        // A: 128 rows x 8 chunks(16B) = 1024 -> 4/thread
#pragma unroll
        for (int i = 0; i < 4; i++) {
            int idx = i * 256 + tid;
            int row = idx >> 3, c = idx & 7;
            cp16(sa + row * ROW_B + c * 16,
                 g_x + (size_t)(m0 + row) * KP + ko + c * 8);
        }
        // B: 128 rows x 8 chunks = 1024 -> 4/thread
#pragma unroll
        for (int i = 0; i < 4; i++) {
            int idx = i * 256 + tid;
            int row = idx >> 3, c = idx & 7;
            cp16(sb + row * ROW_B + c * 16,
                 g_w + (size_t)(n0 + row) * KP + ko + c * 8);
        }
        cp_commit();
    };

    load_stage(0, 0);
    load_stage(1, 1);

    int lrow = lane & 15;
    int acol = (lane >> 4) * 16;
    int b_lrow = (lane & 7) + ((lane >> 4) & 1) * 8;
    int b_lcol = ((lane >> 3) & 1) * 16;

    for (int kc = 0; kc < NKIT; kc++) {
        if (kc + 2 < NKIT) { load_stage((kc + 2) % NSTAGE, kc + 2); cp_wait<2>(); }
        else if (kc + 1 < NKIT) cp_wait<1>();
        else cp_wait<0>();
        __syncthreads();

        uint32_t sa = sbase + (kc % NSTAGE) * STG;
        uint32_t sb = sa + A_STG;

        uint32_t aCur[2][4], aNxt[2][4], bCur[4], bNxt[4];
        // prologue frags: kk=0
#pragma unroll
        for (int t = 0; t < 2; t++)
            ldsm4(aCur[t], sa + (wm + t * 16 + lrow) * ROW_B + acol);
        ldsm4(bCur, sb + (wn + b_lrow) * ROW_B + b_lcol);

#pragma unroll
        for (int kk = 0; kk < 4; kk++) {
            int kb = kk * 32;
            if (kk < 3) {
#pragma unroll
                for (int t = 0; t < 2; t++)
                    ldsm4(aNxt[t], sa + (wm + t * 16 + lrow) * ROW_B + kb + 32 + acol);
            }
#pragma unroll
            for (int jj = 0; jj < 4; jj++) {
                if (jj < 3)
                    ldsm4(bNxt, sb + (wn + (jj + 1) * 16 + b_lrow) * ROW_B + kb + b_lcol);
                else if (kk < 3)
                    ldsm4(bNxt, sb + (wn + b_lrow) * ROW_B + kb + 32 + b_lcol);

                uint32_t be[2] = {bCur[0], bCur[1]}, bo[2] = {bCur[2], bCur[3]};
                int je = jj * 2, jo = jj * 2 + 1;
#pragma unroll
                for (int t = 0; t < 2; t++) {
                    mma16816(acc[t][je], aCur[t], be);
                    mma16816(acc[t][jo], aCur[t], bo);
                }
#pragma unroll
                for (int z = 0; z < 4; z++) bCur[z] = bNxt[z];
            }
            if (kk < 3) {
#pragma unroll
                for (int t = 0; t < 2; t++)
#pragma unroll
                    for (int z = 0; z < 4; z++) aCur[t][z] = aNxt[t][z];
            }
        }
        __syncthreads();
    }

    // ---- epilogue: bias + relu -> g_feat (fp16) ----
    int r2 = lane >> 2, c2 = (lane & 3) * 2;
#pragma unroll
    for (int t = 0; t < 2; t++) {
        int row0 = m0 + wm + t * 16 + r2;
#pragma unroll
        for (int j = 0; j < 8; j++) {
            int col = n0 + wn + j * 8 + c2;
            float b0 = bias[col], b1 = bias[col + 1];
            __half2 v0 = __floats2half2_rn(fmaxf(acc[t][j][0] + b0, 0.0f),
                                           fmaxf(acc[t][j][1] + b1, 0.0f));
            __half2 v1 = __floats2half2_rn(fmaxf(acc[t][j][2] + b0, 0.0f),
                                           fmaxf(acc[t][j][3] + b1, 0.0f));
            *(__half2*)(g_feat + (size_t)row0 * CDIM + col) = v0;
            *(__half2*)(g_feat + (size_t)(row0 + 8) * CDIM + col) = v1;
        }
    }
}

// ---------------- K6: LN2 + output GEMM (6 cols) + biases ----------------
__global__ __launch_bounds__(256) void out_kernel(const float* __restrict__ g2,
                                                  const float* __restrict__ b2,
                                                  const float* __restrict__ out_w,
                                                  const float* __restrict__ out_b,
                                                  float* __restrict__ out) {
    __shared__ float sw[6 * CDIM];
    for (int i = threadIdx.x; i < 6 * CDIM; i += 256) sw[i] = out_w[i];
    __syncthreads();

    int warp = threadIdx.x >> 5;
    int lane = threadIdx.x & 31;
    int row = blockIdx.x * 8 + warp;

    const uint2* f4 = (const uint2*)(g_feat + (size_t)row * CDIM);
    float2 v[16];
    float s = 0.0f;
#pragma unroll
    for (int k = 0; k < 8; k++) {
        uint2 raw = f4[lane + k * 32];
        __half2 lo = *(__half2*)&raw.x;
        __half2 hi = *(__half2*)&raw.y;
        v[2 * k]     = __half22float2(lo);
        v[2 * k + 1] = __half22float2(hi);
        s += v[2 * k].x + v[2 * k].y + v[2 * k + 1].x + v[2 * k + 1].y;
    }
    s = warp_sum(s);
    float mu = s * (1.0f / CDIM);
    float sq = 0.0f;
#pragma unroll
    for (int k = 0; k < 16; k++) {
        float dx = v[k].x - mu, dy = v[k].y - mu;
        sq += dx * dx + dy * dy;
    }
    sq = warp_sum(sq);
    float rs = rsqrtf(sq * (1.0f / CDIM) + EPS);

    float acc[6] = {0, 0, 0, 0, 0, 0};
#pragma unroll
    for (int k = 0; k < 8; k++) {
        int j = (lane + k * 32) * 4;
        float4 gg = *(const float4*)(g2 + j);
        float4 bb = *(const float4*)(b2 + j);
        float y0 = gg.x * (v[2 * k].x - mu) * rs + bb.x;
        float y1 = gg.y * (v[2 * k].y - mu) * rs + bb.y;
        float y2 = gg.z * (v[2 * k + 1].x - mu) * rs + bb.z;
        float y3 = gg.w * (v[2 * k + 1].y - mu) * rs + bb.w;
#pragma unroll
        for (int c = 0; c < 6; c++) {
            const float* swc = sw + c * CDIM + j;
            acc[c] += y0 * swc[0] + y1 * swc[1] + y2 * swc[2] + y3 * swc[3];
        }
    }
#pragma unroll
    for (int c = 0; c < 6; c++) acc[c] = warp_sum(acc[c]);

    if (lane == 0) {
#pragma unroll
        for (int c = 0; c < 6; c++)
            out[row * 6 + c] = acc[c] + out_b[c] + g_bias6[row * 6 + c];
    }
}

// ---------------- launch ----------------
extern "C" void kernel_launch(void* const* d_in, const int* in_sizes, int n_in,
                              void* d_out, int out_size) {
    const float* encode     = (const float*)d_in[0];
    const float* credit_vec = (const float*)d_in[1];
    const float* meta_table = (const float*)d_in[2];
    const float* conv_w     = (const float*)d_in[3];
    const float* conv_b     = (const float*)d_in[4];
    const float* ln1_g      = (const float*)d_in[5];
    const float* ln1_b      = (const float*)d_in[6];
    const float* mlp1_w     = (const float*)d_in[7];
    const float* mlp1_b     = (const float*)d_in[8];
    const float* ln2_g      = (const float*)d_in[9];
    const float* ln2_b      = (const float*)d_in[10];
    const float* out_w      = (const float*)d_in[11];
    const float* out_b      = (const float*)d_in[12];
    const int*   meta_ids   = (const int*)d_in[13];
    const int*   cat_ids    = (const int*)d_in[14];
    const int*   cat_seg    = (const int*)d_in[15];
    float* out = (float*)d_out;

    static bool init = false;
    if (!init) {
        cudaFuncSetAttribute(gemm1_mma, cudaFuncAttributeMaxDynamicSharedMemorySize, SMEM_TOT);
        init = true;
    }

    zero_kernel<<<(BATCH * MD + 255) / 256, 256>>>();
    seg_kernel<<<(NCAT / 8 + 255) / 256, 256>>>(meta_table, cat_ids, cat_seg);
    meta_kernel<<<(BATCH + 127) / 128, 128>>>(meta_table, conv_w, conv_b, meta_ids, credit_vec);
    ln1_kernel<<<BATCH / 8, 256>>>(encode, ln1_g, ln1_b);
    wconv_kernel<<<(CDIM * KP + 255) / 256, 256>>>(mlp1_w);
    {
        dim3 grid(CDIM / B_ROWS, BATCH / A_ROWS);   // (8, 256), N fastest
        gemm1_mma<<<grid, 256, SMEM_TOT>>>(mlp1_b);
    }
    out_kernel<<<BATCH / 8, 256>>>(ln2_g, ln2_b, out_w, out_b, out);
}